// round 2
// baseline (speedup 1.0000x reference)
#include <cuda_runtime.h>

// QuadcopterCollisionFcn:
//   inputs: state (B,N,6) f32, sdf (256,256,256) f32, sdf_grad (unused), T (3,10) f32
//   output: (B,N) f32 in {-10000, 0}
//
// One thread per (b,n). State staged through shared memory with coalesced
// float4 loads. Fully unrolled 10-sample trilerp loop for max MLP on the
// 80 scattered L2 gathers per thread.

#define G 256
#define NPTS 10
#define TPB 256

__global__ __launch_bounds__(TPB)
void quad_collision_kernel(const float* __restrict__ state,
                           const float* __restrict__ sdf,
                           const float* __restrict__ T,   // (3,10) row-major: T[j*10+m]
                           float* __restrict__ out,
                           int total)
{
    __shared__ float s_state[TPB * 6];

    int block_base = blockIdx.x * TPB;

    // Coalesced stage of this block's state rows: TPB*6 floats = TPB*6/4 float4s.
    {
        const float4* src = (const float4*)(state + (size_t)block_base * 6);
        float4* dst = (float4*)s_state;
        int nvec = (TPB * 6) / 4;  // 384
        int avail = (total - block_base) * 6 / 4;  // full blocks only matter; tail guarded
        for (int i = threadIdx.x; i < nvec; i += TPB) {
            if (i < avail) dst[i] = src[i];
        }
    }
    __syncthreads();

    int idx = block_base + threadIdx.x;
    if (idx >= total) return;

    const float* s = s_state + threadIdx.x * 6;
    float px = s[0], py = s[1], pz = s[2];
    float ax = s[3], ay = s[4], az = s[5];

    // Reference: ang = state[...,3:6][::-1] -> (az, ay, ax); R = Rz(az) @ Ry(ay) @ Rx(ax)
    float sz, cz, sy, cy, sx, cx;
    sincosf(az, &sz, &cz);
    sincosf(ay, &sy, &cy);
    sincosf(ax, &sx, &cx);

    float r00 = cz * cy;
    float r01 = cz * sy * sx - sz * cx;
    float r02 = cz * sy * cx + sz * sx;
    float r10 = sz * cy;
    float r11 = sz * sy * sx + cz * cx;
    float r12 = sz * sy * cx - cz * sx;
    float r20 = -sy;
    float r21 = cy * sx;
    float r22 = cy * cx;

    float dmin = 1e30f;

    #pragma unroll
    for (int m = 0; m < NPTS; ++m) {
        // T is (3, NPTS): T[j*NPTS + m] is component j of template point m.
        float t0 = __ldg(&T[0 * NPTS + m]);
        float t1 = __ldg(&T[1 * NPTS + m]);
        float t2 = __ldg(&T[2 * NPTS + m]);

        float X = r00 * t0 + r01 * t1 + r02 * t2 + px;
        float Y = r10 * t0 + r11 * t1 + r12 * t2 + py;
        float Z = r20 * t0 + r21 * t1 + r22 * t2 + pz;

        // clip(p, 0, g-1.000001): f32(254.999999) == 255.0f exactly
        float pcx = fminf(fmaxf(X, 0.0f), 255.0f);
        float pcy = fminf(fmaxf(Y, 0.0f), 255.0f);
        float pcz = fminf(fmaxf(Z, 0.0f), 255.0f);

        int ix = min((int)floorf(pcx), G - 2);
        int iy = min((int)floorf(pcy), G - 2);
        int iz = min((int)floorf(pcz), G - 2);

        float fx = pcx - (float)ix;
        float fy = pcy - (float)iy;
        float fz = pcz - (float)iz;

        int base = (ix << 16) | (iy << 8) | iz;  // ix*G*G + iy*G + iz

        float c000 = __ldg(&sdf[base]);
        float c001 = __ldg(&sdf[base + 1]);
        float c010 = __ldg(&sdf[base + G]);
        float c011 = __ldg(&sdf[base + G + 1]);
        float c100 = __ldg(&sdf[base + G * G]);
        float c101 = __ldg(&sdf[base + G * G + 1]);
        float c110 = __ldg(&sdf[base + G * G + G]);
        float c111 = __ldg(&sdf[base + G * G + G + 1]);

        // Match reference ordering: x-lerp, then y-lerp, then z-lerp
        float omfx = 1.0f - fx;
        float c00 = c000 * omfx + c100 * fx;
        float c01 = c001 * omfx + c101 * fx;
        float c10 = c010 * omfx + c110 * fx;
        float c11 = c011 * omfx + c111 * fx;

        float omfy = 1.0f - fy;
        float c0 = c00 * omfy + c10 * fy;
        float c1 = c01 * omfy + c11 * fy;

        float d = c0 * (1.0f - fz) + c1 * fz;
        dmin = fminf(dmin, d);
    }

    out[idx] = (dmin < 0.0f) ? -10000.0f : 0.0f;
}

extern "C" void kernel_launch(void* const* d_in, const int* in_sizes, int n_in,
                              void* d_out, int out_size)
{
    const float* state = (const float*)d_in[0];
    const float* sdf   = (const float*)d_in[1];
    // d_in[2] = sdf_grad (unused by the reference output)
    const float* T     = (const float*)d_in[3];
    float* out = (float*)d_out;

    int total = in_sizes[0] / 6;  // B*N

    int blocks = (total + TPB - 1) / TPB;
    quad_collision_kernel<<<blocks, TPB>>>(state, sdf, T, out, total);
}

// round 3
// speedup vs baseline: 2.2520x; 2.2520x over previous
#include <cuda_runtime.h>

// QuadcopterCollisionFcn:
//   inputs: state (B,N,6) f32, sdf (256,256,256) f32, sdf_grad (unused), T (3,10) f32
//   output: (B,N) f32 in {-10000, 0}
//
// L1tex-wavefront-optimized version:
//  - z-corner pairs fetched with one aligned float4 (+ rare predicated scalar fixup),
//    extracted bit-exactly with selects -> 4.25 loads/sample instead of 8.
//  - early sign exit: output needs only sign(min d); lanes stop gathering once
//    dmin < 0 (expected ~2 of 10 samples evaluated per lane).
// Position + trilerp arithmetic is expression-identical to the previously
// passing kernel (rel_err == 0.0), so output bits are unchanged.

#define G 256
#define NPTS 10
#define TPB 128

__global__ __launch_bounds__(TPB)
void quad_collision_kernel(const float* __restrict__ state,
                           const float* __restrict__ sdf,
                           const float* __restrict__ T,   // (3,10) row-major: T[j*10+m]
                           float* __restrict__ out,
                           int total)
{
    __shared__ float s_state[TPB * 6];

    int block_base = blockIdx.x * TPB;

    // Coalesced stage of this block's state rows.
    {
        const float4* src = (const float4*)(state + (size_t)block_base * 6);
        float4* dst = (float4*)s_state;
        int nvec = (TPB * 6) / 4;
        int avail = (total - block_base) * 6 / 4;
        for (int i = threadIdx.x; i < nvec; i += TPB) {
            if (i < avail) dst[i] = src[i];
        }
    }
    __syncthreads();

    int idx = block_base + threadIdx.x;
    if (idx >= total) return;

    const float* s = s_state + threadIdx.x * 6;
    float px = s[0], py = s[1], pz = s[2];
    float ax = s[3], ay = s[4], az = s[5];

    // ang = state[...,3:6][::-1] -> (az, ay, ax); R = Rz(az) @ Ry(ay) @ Rx(ax)
    float sz, cz, sy, cy, sx, cx;
    sincosf(az, &sz, &cz);
    sincosf(ay, &sy, &cy);
    sincosf(ax, &sx, &cx);

    float r00 = cz * cy;
    float r01 = cz * sy * sx - sz * cx;
    float r02 = cz * sy * cx + sz * sx;
    float r10 = sz * cy;
    float r11 = sz * sy * sx + cz * cx;
    float r12 = sz * sy * cx - cz * sx;
    float r20 = -sy;
    float r21 = cy * sx;
    float r22 = cy * cx;

    float dmin = 1e30f;

    #pragma unroll
    for (int mb = 0; mb < NPTS; mb += 2) {
        if (dmin >= 0.0f) {       // early sign exit: finished lanes issue no loads
            float dpair = 1e30f;
            #pragma unroll
            for (int mm = 0; mm < 2; ++mm) {
                int m = mb + mm;
                float t0 = __ldg(&T[0 * NPTS + m]);
                float t1 = __ldg(&T[1 * NPTS + m]);
                float t2 = __ldg(&T[2 * NPTS + m]);

                float X = r00 * t0 + r01 * t1 + r02 * t2 + px;
                float Y = r10 * t0 + r11 * t1 + r12 * t2 + py;
                float Z = r20 * t0 + r21 * t1 + r22 * t2 + pz;

                float pcx = fminf(fmaxf(X, 0.0f), 255.0f);
                float pcy = fminf(fmaxf(Y, 0.0f), 255.0f);
                float pcz = fminf(fmaxf(Z, 0.0f), 255.0f);

                int ix = min((int)floorf(pcx), G - 2);
                int iy = min((int)floorf(pcy), G - 2);
                int iz = min((int)floorf(pcz), G - 2);

                float fx = pcx - (float)ix;
                float fy = pcy - (float)iy;
                float fz = pcz - (float)iz;

                int q = iz & ~3;          // 16B-aligned z quad
                int r = iz & 3;
                int base = (ix << 16) | (iy << 8) | q;

                const float4* p4 = (const float4*)(sdf + base);
                float4 F00 = __ldg(p4);                 // (dx=0, dy=0)
                float4 F01 = __ldg(p4 + (G / 4));       // (dx=0, dy=1)
                float4 F10 = __ldg(p4 + (G * G / 4));   // (dx=1, dy=0)
                float4 F11 = __ldg(p4 + (G * G / 4) + (G / 4));

                float e00 = 0.0f, e01 = 0.0f, e10 = 0.0f, e11 = 0.0f;
                if (r == 3) {              // fixup: z+1 spills into next quad (q+4 <= 255)
                    e00 = __ldg(&sdf[base + 4]);
                    e01 = __ldg(&sdf[base + G + 4]);
                    e10 = __ldg(&sdf[base + G * G + 4]);
                    e11 = __ldg(&sdf[base + G * G + G + 4]);
                }

                // bit-exact corner extraction
                float c000 = (r == 0) ? F00.x : (r == 1) ? F00.y : (r == 2) ? F00.z : F00.w;
                float c001 = (r == 0) ? F00.y : (r == 1) ? F00.z : (r == 2) ? F00.w : e00;
                float c010 = (r == 0) ? F01.x : (r == 1) ? F01.y : (r == 2) ? F01.z : F01.w;
                float c011 = (r == 0) ? F01.y : (r == 1) ? F01.z : (r == 2) ? F01.w : e01;
                float c100 = (r == 0) ? F10.x : (r == 1) ? F10.y : (r == 2) ? F10.z : F10.w;
                float c101 = (r == 0) ? F10.y : (r == 1) ? F10.z : (r == 2) ? F10.w : e10;
                float c110 = (r == 0) ? F11.x : (r == 1) ? F11.y : (r == 2) ? F11.z : F11.w;
                float c111 = (r == 0) ? F11.y : (r == 1) ? F11.z : (r == 2) ? F11.w : e11;

                // identical lerp chain to the reference (x, then y, then z)
                float omfx = 1.0f - fx;
                float c00 = c000 * omfx + c100 * fx;
                float c01 = c001 * omfx + c101 * fx;
                float c10 = c010 * omfx + c110 * fx;
                float c11 = c011 * omfx + c111 * fx;

                float omfy = 1.0f - fy;
                float c0 = c00 * omfy + c10 * fy;
                float c1 = c01 * omfy + c11 * fy;

                float d = c0 * (1.0f - fz) + c1 * fz;
                dpair = fminf(dpair, d);
            }
            dmin = fminf(dmin, dpair);
        }
    }

    out[idx] = (dmin < 0.0f) ? -10000.0f : 0.0f;
}

extern "C" void kernel_launch(void* const* d_in, const int* in_sizes, int n_in,
                              void* d_out, int out_size)
{
    const float* state = (const float*)d_in[0];
    const float* sdf   = (const float*)d_in[1];
    // d_in[2] = sdf_grad (unused by the reference output)
    const float* T     = (const float*)d_in[3];
    float* out = (float*)d_out;

    int total = in_sizes[0] / 6;  // B*N

    int blocks = (total + TPB - 1) / TPB;
    quad_collision_kernel<<<blocks, TPB>>>(state, sdf, T, out, total);
}